// round 16
// baseline (speedup 1.0000x reference)
#include <cuda_runtime.h>
#include <cstdint>

#define BB 32
#define TT 4096
#define DD 64
#define HH 128
#define SS 64
#define FEPS 1e-10f

typedef unsigned long long u64;

// ---------------- device scratch (no allocs allowed) ----------------
__device__ float2 g_em2[(size_t)BB * TT * 32];     // emission probs, paired states
__device__ float2 g_alpha2[(size_t)BB * TT * 32];  // forward messages
__device__ float2 g_beta2[(size_t)BB * TT * 32];   // backward messages
__device__ float2 g_Afwd2[32 * 64];  // (A[i][2l], A[i][2l+1]) at [l][i]
__device__ float2 g_Abwd2[32 * 64];  // (A[2l][j], A[2l+1][j]) at [l][j]
__device__ float2 g_pi2[32];
__device__ float  g_partial[(size_t)BB * 256 * SS];  // marginal partials

// ---------------- packed f32x2 helpers ----------------
__device__ __forceinline__ u64 dup2(float x) {
    u64 r; asm("mov.b64 %0, {%1, %1};" : "=l"(r) : "f"(x)); return r;
}
__device__ __forceinline__ void fma2(u64& d, u64 a, u64 b) {
    asm("fma.rn.f32x2 %0, %1, %2, %0;" : "+l"(d) : "l"(a), "l"(b));
}
__device__ __forceinline__ void add2(u64& d, u64 a) {
    asm("add.rn.f32x2 %0, %0, %1;" : "+l"(d) : "l"(a));
}
__device__ __forceinline__ float2 unpk(u64 v) {
    float2 r; asm("mov.b64 {%0, %1}, %2;" : "=f"(r.x), "=f"(r.y) : "l"(v)); return r;
}

// =====================================================================
// 1) prep: transition softmax (+eps), packed A layouts, pi, durations
// =====================================================================
__global__ void prep_kernel(const float* __restrict__ logT,
                            const float* __restrict__ logInit,
                            const float* __restrict__ logR,
                            const float* __restrict__ logitP,
                            float* __restrict__ out_dur) {
    __shared__ float A[SS * SS];
    int tid = threadIdx.x;  // 64 threads
    {
        int i = tid;
        float row[SS];
        float m = -1e30f;
#pragma unroll
        for (int j = 0; j < SS; j++) {
            float v = (j == i) ? -1e10f : logT[i * SS + j];
            row[j] = v; m = fmaxf(m, v);
        }
        float s = 0.f;
#pragma unroll
        for (int j = 0; j < SS; j++) { row[j] = __expf(row[j] - m); s += row[j]; }
        float inv = 1.f / s;
#pragma unroll
        for (int j = 0; j < SS; j++) A[i * SS + j] = fmaf(row[j], inv, FEPS);
    }
    __syncthreads();
    if (tid < 32) {
        int l = tid;
#pragma unroll 4
        for (int i = 0; i < SS; i++) {
            g_Afwd2[l * 64 + i] = make_float2(A[i * SS + 2 * l], A[i * SS + 2 * l + 1]);
            g_Abwd2[l * 64 + i] = make_float2(A[(2 * l) * SS + i], A[(2 * l + 1) * SS + i]);
        }
    }
    if (tid == 0) {
        float m = -1e30f;
        for (int j = 0; j < SS; j++) m = fmaxf(m, logInit[j]);
        float e[SS]; float s = 0.f;
        for (int j = 0; j < SS; j++) { e[j] = __expf(logInit[j] - m); s += e[j]; }
        float inv = 1.f / s;
        for (int j = 0; j < 32; j++)
            g_pi2[j] = make_float2(e[2 * j] * inv, e[2 * j + 1] * inv);
    }
    if (tid < SS) {
        float r = expf(logR[tid]);
        float p = 1.f / (1.f + expf(-logitP[tid]));
        out_dur[tid] = r * (1.f - p) / p;
    }
}

// =====================================================================
// 2) emission MLP v2: packed f32x2, dup-staged activations in smem
//    smem: W1 8192f | W2 16384f | W3 8192f | b1 128 | b2 128 | b3 64
//          | 8 warps x 768 u64 staging ([xd 256][h1d 512], h2d overlays 0..512)
// =====================================================================
#define MLP_SMEM_BYTES (33088 * 4 + 8 * 768 * 8)  // 181504

// stage one relu'd f32x2 pair (outputs o, o+1) for row r as dup-pairs
#define STAGE_PAIR(dst, o, r, reg) {                                  \
    float2 _v = unpk(reg);                                            \
    (dst)[(size_t)(o) * 4 + (r)]       = dup2(fmaxf(_v.x, 0.f));      \
    (dst)[(size_t)((o) + 1) * 4 + (r)] = dup2(fmaxf(_v.y, 0.f)); }

__global__ __launch_bounds__(256) void mlp_kernel(
    const float* __restrict__ obs,
    const float* __restrict__ W1, const float* __restrict__ b1,
    const float* __restrict__ W2, const float* __restrict__ b2,
    const float* __restrict__ W3, const float* __restrict__ b3) {
    extern __shared__ float sm[];
    float* W1s = sm;
    float* W2s = sm + 8192;
    float* W3s = sm + 24576;
    float* b1s = sm + 32768;
    float* b2s = sm + 32896;
    float* b3s = sm + 33024;
    u64* stage = (u64*)(sm + 33088);

    int tid = threadIdx.x, w = tid >> 5, l = tid & 31;

    for (int i = tid; i < 8192 / 4; i += 256) ((float4*)W1s)[i] = ((const float4*)W1)[i];
    for (int i = tid; i < 16384 / 4; i += 256) ((float4*)W2s)[i] = ((const float4*)W2)[i];
    for (int i = tid; i < 8192 / 4; i += 256) ((float4*)W3s)[i] = ((const float4*)W3)[i];
    if (tid < 128) { b1s[tid] = b1[tid]; b2s[tid] = b2[tid]; }
    if (tid < 64) b3s[tid] = b3[tid];
    __syncthreads();

    u64* xd  = stage + (size_t)w * 768;  // [k*4 + r], k<64
    u64* h1d = xd + 256;                 // [k*4 + r], k<128
    u64* h2d = xd;                       // overlays [0,512): valid after L2 done

    const ulonglong2* W1p = (const ulonglong2*)W1s + l;  // [k*32 + l]
    const ulonglong2* W2p = (const ulonglong2*)W2s + l;
    const u64*        W3p = (const u64*)W3s + l;
    u64 b1A = ((const u64*)b1s)[2 * l], b1B = ((const u64*)b1s)[2 * l + 1];
    u64 b2A = ((const u64*)b2s)[2 * l], b2B = ((const u64*)b2s)[2 * l + 1];
    u64 b3P = ((const u64*)b3s)[l];

    const int nrb = (BB * TT) / 32;
    for (int rb = blockIdx.x; rb < nrb; rb += gridDim.x) {
        int base = rb * 32 + w * 4;
        __syncwarp();  // previous iteration's h2d reads done before xd overwrite

        // ---- stage x (4 rows x 64) as dup-pairs ----
        {
            const float4* ob = (const float4*)(obs + (size_t)base * DD);
            float4 v = ob[l];
            int r = l >> 4, k4 = l & 15;
            u64* p = xd + (size_t)(4 * k4) * 4 + r;
            p[0] = dup2(v.x); p[4] = dup2(v.y); p[8] = dup2(v.z); p[12] = dup2(v.w);
            v = ob[l + 32];
            int f = l + 32; r = f >> 4; k4 = f & 15;
            p = xd + (size_t)(4 * k4) * 4 + r;
            p[0] = dup2(v.x); p[4] = dup2(v.y); p[8] = dup2(v.z); p[12] = dup2(v.w);
        }
        __syncwarp();

        // ---- layer 1: (4 x 64) @ (64 x 128); lane owns outputs 4l..4l+3 ----
        u64 q00 = b1A, q01 = b1B, q10 = b1A, q11 = b1B;
        u64 q20 = b1A, q21 = b1B, q30 = b1A, q31 = b1B;
#pragma unroll 8
        for (int k = 0; k < DD; k++) {
            ulonglong2 wv  = W1p[k * 32];
            ulonglong2 x01 = *(const ulonglong2*)(xd + k * 4);
            ulonglong2 x23 = *(const ulonglong2*)(xd + k * 4 + 2);
            fma2(q00, wv.x, x01.x); fma2(q01, wv.y, x01.x);
            fma2(q10, wv.x, x01.y); fma2(q11, wv.y, x01.y);
            fma2(q20, wv.x, x23.x); fma2(q21, wv.y, x23.x);
            fma2(q30, wv.x, x23.y); fma2(q31, wv.y, x23.y);
        }
        STAGE_PAIR(h1d, 4 * l, 0, q00) STAGE_PAIR(h1d, 4 * l + 2, 0, q01)
        STAGE_PAIR(h1d, 4 * l, 1, q10) STAGE_PAIR(h1d, 4 * l + 2, 1, q11)
        STAGE_PAIR(h1d, 4 * l, 2, q20) STAGE_PAIR(h1d, 4 * l + 2, 2, q21)
        STAGE_PAIR(h1d, 4 * l, 3, q30) STAGE_PAIR(h1d, 4 * l + 2, 3, q31)
        __syncwarp();

        // ---- layer 2: (4 x 128) @ (128 x 128) ----
        q00 = b2A; q01 = b2B; q10 = b2A; q11 = b2B;
        q20 = b2A; q21 = b2B; q30 = b2A; q31 = b2B;
#pragma unroll 8
        for (int k = 0; k < HH; k++) {
            ulonglong2 wv  = W2p[k * 32];
            ulonglong2 x01 = *(const ulonglong2*)(h1d + k * 4);
            ulonglong2 x23 = *(const ulonglong2*)(h1d + k * 4 + 2);
            fma2(q00, wv.x, x01.x); fma2(q01, wv.y, x01.x);
            fma2(q10, wv.x, x01.y); fma2(q11, wv.y, x01.y);
            fma2(q20, wv.x, x23.x); fma2(q21, wv.y, x23.x);
            fma2(q30, wv.x, x23.y); fma2(q31, wv.y, x23.y);
        }
        __syncwarp();  // all h1d reads done before h2d overlay write
        STAGE_PAIR(h2d, 4 * l, 0, q00) STAGE_PAIR(h2d, 4 * l + 2, 0, q01)
        STAGE_PAIR(h2d, 4 * l, 1, q10) STAGE_PAIR(h2d, 4 * l + 2, 1, q11)
        STAGE_PAIR(h2d, 4 * l, 2, q20) STAGE_PAIR(h2d, 4 * l + 2, 2, q21)
        STAGE_PAIR(h2d, 4 * l, 3, q30) STAGE_PAIR(h2d, 4 * l + 2, 3, q31)
        __syncwarp();

        // ---- layer 3: (4 x 128) @ (128 x 64); lane owns outputs 2l,2l+1 ----
        u64 c0 = b3P, c1 = b3P, c2 = b3P, c3 = b3P;
#pragma unroll 8
        for (int k = 0; k < HH; k++) {
            u64 wv = W3p[k * 32];
            ulonglong2 x01 = *(const ulonglong2*)(h2d + k * 4);
            ulonglong2 x23 = *(const ulonglong2*)(h2d + k * 4 + 2);
            fma2(c0, wv, x01.x); fma2(c1, wv, x01.y);
            fma2(c2, wv, x23.x); fma2(c3, wv, x23.y);
        }
        float2 r0 = unpk(c0), r1 = unpk(c1), r2 = unpk(c2), r3 = unpk(c3);

        // ---- softmax over 64 states (interleaved butterflies) ----
        float m0 = fmaxf(r0.x, r0.y), m1 = fmaxf(r1.x, r1.y);
        float m2 = fmaxf(r2.x, r2.y), m3 = fmaxf(r3.x, r3.y);
#pragma unroll
        for (int d = 16; d; d >>= 1) {
            m0 = fmaxf(m0, __shfl_xor_sync(0xffffffffu, m0, d));
            m1 = fmaxf(m1, __shfl_xor_sync(0xffffffffu, m1, d));
            m2 = fmaxf(m2, __shfl_xor_sync(0xffffffffu, m2, d));
            m3 = fmaxf(m3, __shfl_xor_sync(0xffffffffu, m3, d));
        }
        float e00 = __expf(r0.x - m0), e01 = __expf(r0.y - m0);
        float e10 = __expf(r1.x - m1), e11 = __expf(r1.y - m1);
        float e20 = __expf(r2.x - m2), e21 = __expf(r2.y - m2);
        float e30 = __expf(r3.x - m3), e31 = __expf(r3.y - m3);
        float s0 = e00 + e01, s1 = e10 + e11, s2 = e20 + e21, s3 = e30 + e31;
#pragma unroll
        for (int d = 16; d; d >>= 1) {
            s0 += __shfl_xor_sync(0xffffffffu, s0, d);
            s1 += __shfl_xor_sync(0xffffffffu, s1, d);
            s2 += __shfl_xor_sync(0xffffffffu, s2, d);
            s3 += __shfl_xor_sync(0xffffffffu, s3, d);
        }
        float i0 = 1.f / s0, i1 = 1.f / s1, i2 = 1.f / s2, i3 = 1.f / s3;
        g_em2[(size_t)(base + 0) * 32 + l] = make_float2(e00 * i0, e01 * i0);
        g_em2[(size_t)(base + 1) * 32 + l] = make_float2(e10 * i1, e11 * i1);
        g_em2[(size_t)(base + 2) * 32 + l] = make_float2(e20 * i2, e21 * i2);
        g_em2[(size_t)(base + 3) * 32 + l] = make_float2(e30 * i3, e31 * i3);
    }
}

// =====================================================================
// 3) recursions v3: ONE warp per (b,dir); A column-pairs in 128 regs,
//    8 independent f32x2 accumulators (32-cyc chain), no block barrier,
//    4-deep emission prefetch, lane0-scale renorm every 4 steps
//    (applied scale tracked exactly in double for the LL; any per-t
//    scale cancels in gamma).
// =====================================================================

#define RMATVEC                                                          \
    u64 ae0=0,ae1=0,ae2=0,ae3=0,ao0=0,ao1=0,ao2=0,ao3=0;                 \
    _Pragma("unroll") for (int j = 0; j < 8; j++) {                      \
        ulonglong2 v0 = bp[4*j], v1 = bp[4*j+1];                         \
        ulonglong2 v2 = bp[4*j+2], v3 = bp[4*j+3];                       \
        fma2(ae0, cp[8*j+0], v0.x); fma2(ao0, cp[8*j+1], v0.y);          \
        fma2(ae1, cp[8*j+2], v1.x); fma2(ao1, cp[8*j+3], v1.y);          \
        fma2(ae2, cp[8*j+4], v2.x); fma2(ao2, cp[8*j+5], v2.y);          \
        fma2(ae3, cp[8*j+6], v3.x); fma2(ao3, cp[8*j+7], v3.y);          \
    }                                                                    \
    add2(ae0, ae1); add2(ae2, ae3); add2(ao0, ao1); add2(ao2, ao3);      \
    add2(ae0, ae2); add2(ao0, ao2); add2(ae0, ao0);

#define FSTEP(T, EV, RN) {                                               \
    const ulonglong2* bp = buf2[((T) + 1) & 1];                          \
    RMATVEC                                                              \
    float2 sv = unpk(ae0);                                               \
    a0 = sv.x * ((EV).x + FEPS); a1 = sv.y * ((EV).y + FEPS);            \
    AL[(size_t)(T) * 32] = make_float2(a0, a1);                          \
    if (RN) {                                                            \
        float s0 = a0 + a1;                                              \
        float sb = __shfl_sync(0xffffffffu, s0, 0);                      \
        float inv = 1.f / sb; a0 *= inv; a1 *= inv;                      \
        c += (double)__logf(sb);                                         \
    }                                                                    \
    buf2[(T) & 1][l] = make_ulonglong2(dup2(a0), dup2(a1));              \
    __syncwarp(); }

#define BSTEP(T, EV, RN) {                                               \
    const ulonglong2* bp = buf2[((T) + 1) & 1];                          \
    RMATVEC                                                              \
    float2 sv = unpk(ae0);                                               \
    float b0 = sv.x, b1 = sv.y;                                          \
    BL[(size_t)(T) * 32] = make_float2(b0, b1);                          \
    if (RN) {                                                            \
        float s0 = b0 + b1;                                              \
        float sb = __shfl_sync(0xffffffffu, s0, 0);                      \
        float inv = 1.f / sb; b0 *= inv; b1 *= inv;                      \
    }                                                                    \
    float v0 = b0 * ((EV).x + FEPS), v1 = b1 * ((EV).y + FEPS);          \
    buf2[(T) & 1][l] = make_ulonglong2(dup2(v0), dup2(v1));              \
    __syncwarp(); }

__global__ __launch_bounds__(32) void recur_kernel(float* __restrict__ d_ll) {
    int id = blockIdx.x;  // 64 = 32 batches x 2 directions
    int b = id >> 1;
    bool bwd = (id & 1) != 0;
    int l = threadIdx.x;

    __shared__ __align__(16) ulonglong2 buf2[2][32];

    u64 cp[64];
    const u64* M = (const u64*)(bwd ? g_Abwd2 : g_Afwd2) + (size_t)l * 64;
#pragma unroll
    for (int i = 0; i < 64; i++) cp[i] = M[i];

    const float2* E = g_em2 + (size_t)b * TT * 32 + l;

    if (!bwd) {
        float2* AL = g_alpha2 + (size_t)b * TT * 32 + l;
        float2 pp = g_pi2[l];
        float2 e0 = E[0];
        float a0 = pp.x * e0.x, a1 = pp.y * e0.y;  // t=0: NO eps (matches ref)
        AL[0] = make_float2(a0, a1);
        buf2[0][l] = make_ulonglong2(dup2(a0), dup2(a1));
        __syncwarp();
        double c = 0.0;
        float2 eA0 = E[32], eA1 = E[64], eA2 = E[96], eA3 = E[128];
        for (int t0 = 1; t0 + 7 < TT; t0 += 4) {
            float2 eB0 = E[(size_t)(t0 + 4) * 32], eB1 = E[(size_t)(t0 + 5) * 32];
            float2 eB2 = E[(size_t)(t0 + 6) * 32], eB3 = E[(size_t)(t0 + 7) * 32];
            FSTEP(t0, eA0, 0)
            FSTEP(t0 + 1, eA1, 0)
            FSTEP(t0 + 2, eA2, 0)
            FSTEP(t0 + 3, eA3, 1)
            eA0 = eB0; eA1 = eB1; eA2 = eB2; eA3 = eB3;
        }
        // after loop: eA holds E[4089..4092]
        FSTEP(4089, eA0, 0)
        FSTEP(4090, eA1, 0)
        FSTEP(4091, eA2, 0)
        FSTEP(4092, eA3, 1)
        float2 ex = E[(size_t)4093 * 32];
        FSTEP(4093, ex, 0)
        ex = E[(size_t)4094 * 32];
        FSTEP(4094, ex, 0)
        ex = E[(size_t)4095 * 32];
        FSTEP(4095, ex, 0)
        float sum = a0 + a1;
#pragma unroll
        for (int d = 16; d; d >>= 1) sum += __shfl_xor_sync(0xffffffffu, sum, d);
        if (l == 0) d_ll[b] = __logf(sum) + (float)c;
    } else {
        float2* BL = g_beta2 + (size_t)b * TT * 32 + l;
        float2 eL = E[(size_t)(TT - 1) * 32];
        BL[(size_t)(TT - 1) * 32] = make_float2(1.f, 1.f);
        buf2[(TT - 1) & 1][l] =
            make_ulonglong2(dup2(eL.x + FEPS), dup2(eL.y + FEPS));
        __syncwarp();
        float2 eA0 = E[(size_t)4094 * 32], eA1 = E[(size_t)4093 * 32];
        float2 eA2 = E[(size_t)4092 * 32], eA3 = E[(size_t)4091 * 32];
        for (int t0 = 4094; t0 - 7 >= 0; t0 -= 4) {
            float2 eB0 = E[(size_t)(t0 - 4) * 32], eB1 = E[(size_t)(t0 - 5) * 32];
            float2 eB2 = E[(size_t)(t0 - 6) * 32], eB3 = E[(size_t)(t0 - 7) * 32];
            BSTEP(t0, eA0, 0)
            BSTEP(t0 - 1, eA1, 0)
            BSTEP(t0 - 2, eA2, 0)
            BSTEP(t0 - 3, eA3, 1)
            eA0 = eB0; eA1 = eB1; eA2 = eB2; eA3 = eB3;
        }
        // after loop: eA holds E[6,5,4,3]
        BSTEP(6, eA0, 0)
        BSTEP(5, eA1, 0)
        BSTEP(4, eA2, 0)
        BSTEP(3, eA3, 1)
        float2 ex = E[(size_t)2 * 32];
        BSTEP(2, ex, 0)
        ex = E[32];
        BSTEP(1, ex, 0)
        ex = E[0];
        BSTEP(0, ex, 0)
    }
}

// =====================================================================
// 4) gamma + deterministic marginal partials (warp per row)
// =====================================================================
__global__ __launch_bounds__(256) void gamma_kernel(float* __restrict__ outp) {
    int w = threadIdx.x >> 5, l = threadIdx.x & 31;
    int R0 = blockIdx.x * 128;
    int rowbase = R0 + w * 16;
    float2* O2 = (float2*)outp;
    float m0 = 0.f, m1 = 0.f;
    for (int i = 0; i < 16; i++) {
        size_t row = (size_t)(rowbase + i);
        float2 a = g_alpha2[row * 32 + l];
        float2 bb = g_beta2[row * 32 + l];
        float gg0 = a.x * bb.x, gg1 = a.y * bb.y;
        float s = gg0 + gg1;
#pragma unroll
        for (int d = 16; d; d >>= 1) s += __shfl_xor_sync(0xffffffffu, s, d);
        float inv = 1.f / s;
        gg0 *= inv; gg1 *= inv;
        O2[row * 32 + l] = make_float2(gg0, gg1);
        m0 += gg0; m1 += gg1;
    }
    int b = R0 >> 12;
    int chunk = ((R0 & 4095) >> 4) + w;
    float* P = g_partial + ((size_t)b * 256 + chunk) * SS;
    P[2 * l] = m0;
    P[2 * l + 1] = m1;
}

__global__ void fin_kernel(float* __restrict__ out_marg) {
    int gid = blockIdx.x * 256 + threadIdx.x;
    int b = gid >> 6, s = gid & 63;
    const float* P = g_partial + (size_t)b * 256 * SS + s;
    float acc = 0.f;
#pragma unroll 8
    for (int k = 0; k < 256; k++) acc += P[k * SS];
    out_marg[gid] = acc * (1.f / TT);
}

// =====================================================================
extern "C" void kernel_launch(void* const* d_in, const int* in_sizes, int n_in,
                              void* d_out, int out_size) {
    const float* obs     = (const float*)d_in[0];
    const float* W1      = (const float*)d_in[1];
    const float* b1      = (const float*)d_in[2];
    const float* W2      = (const float*)d_in[3];
    const float* b2      = (const float*)d_in[4];
    const float* W3      = (const float*)d_in[5];
    const float* b3      = (const float*)d_in[6];
    const float* logT    = (const float*)d_in[7];
    const float* logInit = (const float*)d_in[8];
    const float* logR    = (const float*)d_in[9];
    const float* logitP  = (const float*)d_in[10];

    float* out = (float*)d_out;
    float* out_sp   = out;                         // (B,T,S)
    float* out_marg = out + (size_t)BB * TT * SS;  // (B,S)
    float* out_dur  = out_marg + BB * SS;          // (S,)
    float* out_ll   = out_dur + SS;                // (B,)

    cudaFuncSetAttribute(mlp_kernel, cudaFuncAttributeMaxDynamicSharedMemorySize,
                         MLP_SMEM_BYTES);

    prep_kernel<<<1, 64>>>(logT, logInit, logR, logitP, out_dur);
    mlp_kernel<<<148, 256, MLP_SMEM_BYTES>>>(obs, W1, b1, W2, b2, W3, b3);
    recur_kernel<<<64, 32>>>(out_ll);
    gamma_kernel<<<(BB * TT) / 128, 256>>>(out_sp);
    fin_kernel<<<8, 256>>>(out_marg);
}